// round 6
// baseline (speedup 1.0000x reference)
#include <cuda_runtime.h>
#include <cstdint>

#define K_TOP    30
#define EMB_DIM  128
#define NT_A     128   // 4 warps per block for the top-k kernel
#define NT_B     256
#define NGRAPH   2048

// Scratch: global node index of rank-r element per graph, -1 if invalid.
__device__ int g_tops[NGRAPH * 32];

// Map float -> uint32 whose unsigned order matches float order (ascending).
__device__ __forceinline__ unsigned int float_to_sortable(float f) {
    unsigned int b = __float_as_uint(f);
    return (b & 0x80000000u) ? ~b : (b | 0x80000000u);
}

__device__ __forceinline__ unsigned long long shflx64(unsigned long long x, int m) {
    unsigned lo = (unsigned)x, hi = (unsigned)(x >> 32);
    lo = __shfl_xor_sync(0xffffffffu, lo, m);
    hi = __shfl_xor_sync(0xffffffffu, hi, m);
    return ((unsigned long long)hi << 32) | lo;
}

__device__ __forceinline__ unsigned long long cmpx(unsigned long long a,
                                                   unsigned long long b,
                                                   bool keep_max) {
    unsigned long long mx = a > b ? a : b;
    unsigned long long mn = a > b ? b : a;
    return keep_max ? mx : mn;
}

// 5-stage descending bitonic merge (32-wide) of a bitonic sequence.
__device__ __forceinline__ unsigned long long warp_merge_desc(unsigned long long key,
                                                              int lane) {
    #pragma unroll
    for (int j = 16; j >= 1; j >>= 1) {
        bool lower = (lane & j) == 0;
        unsigned long long other = shflx64(key, j);
        key = cmpx(key, other, lower);
    }
    return key;
}

// ---------------- Kernel A: per-graph top-K selection ----------------
__global__ void __launch_bounds__(NT_A)
topk_kernel(const float* __restrict__ emb,
            const int*   __restrict__ sizes,
            float*       __restrict__ out,
            int G) {
    const int g    = blockIdx.x;
    const int tid  = threadIdx.x;
    const int lane = tid & 31;
    const int wid  = tid >> 5;

    __shared__ unsigned long long s[NT_A];
    __shared__ int wsum[NT_A / 32];
    __shared__ int sh_off;

    // ---- offset = prefix sum of sizes[0..g-1], int4-vectorized (L2-resident) ----
    int acc = 0;
    {
        const int4* s4 = (const int4*)sizes;
        const int nfull = g >> 2;
        for (int j = tid; j < nfull; j += NT_A) {
            int4 v = s4[j];
            acc += v.x + v.y + v.z + v.w;
        }
        if (tid < (g & 3)) acc += sizes[(nfull << 2) + tid];
    }
    #pragma unroll
    for (int m = 16; m; m >>= 1) acc += __shfl_xor_sync(0xffffffffu, acc, m);
    if (lane == 0) wsum[wid] = acc;
    __syncthreads();
    if (tid == 0) {
        int o = 0;
        #pragma unroll
        for (int w = 0; w < NT_A / 32; w++) o += wsum[w];
        sh_off = o;
    }
    __syncthreads();
    const int offset = sh_off;
    const int size   = sizes[g];
    const int nw64   = (size + 63) >> 6;   // warps holding data (64 elems each)

    // Composite keys: (sortable(val) << 32) | ~elem_idx. Descending composite
    // order == descending value, ascending index on ties. Lane holds elements
    // i0 = wid*64+lane (key0) and i1 = wid*64+32+lane (key1).
    const int i0 = (wid << 6) + lane;
    const int i1 = i0 + 32;
    unsigned long long key0 = (unsigned long long)(unsigned int)(~(unsigned int)i0);
    unsigned long long key1 = (unsigned long long)(unsigned int)(~(unsigned int)i1);

    if (wid < nw64) {
        if (i0 < size) {
            float v = __ldg(&emb[(size_t)(offset + i0) * EMB_DIM + (EMB_DIM - 1)]);
            key0 |= (unsigned long long)float_to_sortable(v) << 32;
        }
        if (i1 < size) {
            float v = __ldg(&emb[(size_t)(offset + i1) * EMB_DIM + (EMB_DIM - 1)]);
            key1 |= (unsigned long long)float_to_sortable(v) << 32;
        }

        // ---- 64-element bitonic sort (descending), 2 keys per lane ----
        #pragma unroll
        for (int k = 2; k <= 16; k <<= 1) {
            const bool dir = ((lane & k) == 0);
            #pragma unroll
            for (int j = k >> 1; j >= 1; j >>= 1) {
                bool lower = (lane & j) == 0;
                key0 = cmpx(key0, shflx64(key0, j), lower == dir);
                key1 = cmpx(key1, shflx64(key1, j), lower == dir);
            }
        }
        // k = 32: key0 half descending, key1 half ascending.
        #pragma unroll
        for (int j = 16; j >= 1; j >>= 1) {
            bool lower = (lane & j) == 0;
            key0 = cmpx(key0, shflx64(key0, j), lower);
            key1 = cmpx(key1, shflx64(key1, j), !lower);
        }
        // k = 64: j=32 is intra-thread, then 5-stage descending merge (top half).
        {
            unsigned long long mx = key0 > key1 ? key0 : key1;
            key0 = warp_merge_desc(mx, lane);
        }
        // Warp's top-32 (of its 64) now in key0, descending.
        s[(wid << 5) + lane] = key0;
    }
    __syncthreads();

    // ---- top-32 merge tree over nw64 sorted runs ----
    for (int step = 1; step < nw64; step <<= 1) {
        bool winner = ((wid & (2 * step - 1)) == 0) && (wid + step < nw64);
        if (winner) {
            unsigned long long other = s[((wid + step) << 5) + (31 - lane)];
            key0 = key0 > other ? key0 : other;
            key0 = warp_merge_desc(key0, lane);
            s[(wid << 5) + lane] = key0;
        }
        __syncthreads();
    }

    // ---- warp 0 lane r holds rank-r key; publish global indices ----
    const int kmax = min(K_TOP, size);
    if (wid == 0) {
        int lidx = (int)(~(unsigned int)(key0 & 0xFFFFFFFFull));
        int gidx = (lane < kmax) ? (offset + lidx) : -1;
        g_tops[(g << 5) + lane] = gidx;
        if (lane < K_TOP) {
            __stcs(&out[(size_t)G * K_TOP * EMB_DIM + (size_t)g * K_TOP + lane],
                   (float)gidx);
        }
    }
}

// ---------------- Kernel B: pure streaming gather ----------------
// 32 output rows per block; warp w owns rows {b*32+w, +8, +16, +24},
// all 4 LDG.128 issued back-to-back (MLP=4 per warp).
__global__ void __launch_bounds__(NT_B)
gather_kernel(const float* __restrict__ emb,
              float*       __restrict__ out) {
    const int lane = threadIdx.x & 31;
    const int wid  = threadIdx.x >> 5;
    const int rowb = blockIdx.x * 32;

    const float4* emb4 = (const float4*)emb;
    float4*       out4 = (float4*)out;
    const float4  zero = make_float4(0.f, 0.f, 0.f, 0.f);

    const int r0 = rowb + wid;
    const int r1 = r0 + 8;
    const int r2 = r0 + 16;
    const int r3 = r0 + 24;

    // row -> (graph, k) ; compiler turns /30 into a magic multiply.
    const unsigned q0 = (unsigned)r0 / 30u, k0 = (unsigned)r0 - q0 * 30u;
    const unsigned q1 = (unsigned)r1 / 30u, k1 = (unsigned)r1 - q1 * 30u;
    const unsigned q2 = (unsigned)r2 / 30u, k2 = (unsigned)r2 - q2 * 30u;
    const unsigned q3 = (unsigned)r3 / 30u, k3 = (unsigned)r3 - q3 * 30u;

    const int i0 = g_tops[(q0 << 5) + k0];
    const int i1 = g_tops[(q1 << 5) + k1];
    const int i2 = g_tops[(q2 << 5) + k2];
    const int i3 = g_tops[(q3 << 5) + k3];

    float4 v0 = (i0 >= 0) ? __ldg(&emb4[(size_t)i0 * 32 + lane]) : zero;
    float4 v1 = (i1 >= 0) ? __ldg(&emb4[(size_t)i1 * 32 + lane]) : zero;
    float4 v2 = (i2 >= 0) ? __ldg(&emb4[(size_t)i2 * 32 + lane]) : zero;
    float4 v3 = (i3 >= 0) ? __ldg(&emb4[(size_t)i3 * 32 + lane]) : zero;

    __stcs(&out4[(size_t)r0 * 32 + lane], v0);
    __stcs(&out4[(size_t)r1 * 32 + lane], v1);
    __stcs(&out4[(size_t)r2 * 32 + lane], v2);
    __stcs(&out4[(size_t)r3 * 32 + lane], v3);
}

extern "C" void kernel_launch(void* const* d_in, const int* in_sizes, int n_in,
                              void* d_out, int out_size) {
    const float* emb   = (const float*)d_in[0];
    const int*   sizes = (const int*)d_in[1];
    const int G = in_sizes[1];

    topk_kernel<<<G, NT_A>>>(emb, sizes, (float*)d_out, G);
    // G*K_TOP rows total, 32 rows per block (G*30 divisible by 32 for G=2048)
    const int nrows  = G * K_TOP;
    const int blocks = (nrows + 31) / 32;
    gather_kernel<<<blocks, NT_B>>>(emb, (float*)d_out);
}

// round 7
// speedup vs baseline: 1.2576x; 1.2576x over previous
#include <cuda_runtime.h>
#include <cstdint>

#define K_TOP    30
#define EMB_DIM  128
#define NT       128   // 4 warps per block

// Map float -> uint32 whose unsigned order matches float order (ascending).
__device__ __forceinline__ unsigned int float_to_sortable(float f) {
    unsigned int b = __float_as_uint(f);
    return (b & 0x80000000u) ? ~b : (b | 0x80000000u);
}

__device__ __forceinline__ unsigned long long shflx64(unsigned long long x, int m) {
    unsigned lo = (unsigned)x, hi = (unsigned)(x >> 32);
    lo = __shfl_xor_sync(0xffffffffu, lo, m);
    hi = __shfl_xor_sync(0xffffffffu, hi, m);
    return ((unsigned long long)hi << 32) | lo;
}

__device__ __forceinline__ unsigned long long cmpx(unsigned long long a,
                                                   unsigned long long b,
                                                   bool keep_max) {
    unsigned long long mx = a > b ? a : b;
    unsigned long long mn = a > b ? b : a;
    return keep_max ? mx : mn;
}

// 5-stage descending bitonic merge (32-wide) of a bitonic sequence.
__device__ __forceinline__ unsigned long long warp_merge_desc(unsigned long long key,
                                                              int lane) {
    #pragma unroll
    for (int j = 16; j >= 1; j >>= 1) {
        bool lower = (lane & j) == 0;
        unsigned long long other = shflx64(key, j);
        key = cmpx(key, other, lower);
    }
    return key;
}

__global__ void __launch_bounds__(NT)
sortpool_kernel(const float* __restrict__ emb,
                const int*   __restrict__ sizes,
                float*       __restrict__ out,
                int G) {
    const int g    = blockIdx.x;
    const int tid  = threadIdx.x;
    const int lane = tid & 31;
    const int wid  = tid >> 5;

    __shared__ unsigned long long s[NT];      // one 32-slot run per warp
    __shared__ int wsum[NT / 32];
    __shared__ int sh_off;
    __shared__ int tops[32];

    // ---- offset = prefix sum of sizes[0..g-1], int4-vectorized (L2-resident) ----
    int acc = 0;
    {
        const int4* s4 = (const int4*)sizes;
        const int nfull = g >> 2;
        for (int j = tid; j < nfull; j += NT) {
            int4 v = s4[j];
            acc += v.x + v.y + v.z + v.w;
        }
        if (tid < (g & 3)) acc += sizes[(nfull << 2) + tid];
    }
    #pragma unroll
    for (int m = 16; m; m >>= 1) acc += __shfl_xor_sync(0xffffffffu, acc, m);
    if (lane == 0) wsum[wid] = acc;
    __syncthreads();
    if (tid == 0) {
        int o = 0;
        #pragma unroll
        for (int w = 0; w < NT / 32; w++) o += wsum[w];
        sh_off = o;
    }
    __syncthreads();
    const int offset = sh_off;
    const int size   = sizes[g];
    const int nw64   = (size + 63) >> 6;   // warps holding data (64 elems each)

    // Composite keys: (sortable(val) << 32) | ~elem_idx. Descending composite
    // order == descending value, ascending index on ties. Lane holds elements
    // i0 = wid*64+lane (key0) and i1 = wid*64+32+lane (key1).
    const int i0 = (wid << 6) + lane;
    const int i1 = i0 + 32;
    unsigned long long key0 = (unsigned long long)(unsigned int)(~(unsigned int)i0);
    unsigned long long key1 = (unsigned long long)(unsigned int)(~(unsigned int)i1);

    if (wid < nw64) {
        if (i0 < size) {
            float v = __ldg(&emb[(size_t)(offset + i0) * EMB_DIM + (EMB_DIM - 1)]);
            key0 |= (unsigned long long)float_to_sortable(v) << 32;
        }
        if (i1 < size) {
            float v = __ldg(&emb[(size_t)(offset + i1) * EMB_DIM + (EMB_DIM - 1)]);
            key1 |= (unsigned long long)float_to_sortable(v) << 32;
        }

        // ---- 64-element bitonic sort (descending), 2 keys per lane ----
        #pragma unroll
        for (int k = 2; k <= 16; k <<= 1) {
            const bool dir = ((lane & k) == 0);
            #pragma unroll
            for (int j = k >> 1; j >= 1; j >>= 1) {
                bool lower = (lane & j) == 0;
                key0 = cmpx(key0, shflx64(key0, j), lower == dir);
                key1 = cmpx(key1, shflx64(key1, j), lower == dir);
            }
        }
        // k = 32: key0 half descending, key1 half ascending.
        #pragma unroll
        for (int j = 16; j >= 1; j >>= 1) {
            bool lower = (lane & j) == 0;
            key0 = cmpx(key0, shflx64(key0, j), lower);
            key1 = cmpx(key1, shflx64(key1, j), !lower);
        }
        // k = 64: j=32 is intra-thread (keep max half), then clean with a
        // 5-stage descending merge. Warp's top-32 of its 64 lands in key0.
        {
            unsigned long long mx = key0 > key1 ? key0 : key1;
            key0 = warp_merge_desc(mx, lane);
        }
        s[(wid << 5) + lane] = key0;
    }
    __syncthreads();

    // ---- top-32 merge tree over nw64 sorted runs ----
    // Top-32 of two descending runs: max(a[lane], b[31-lane]) is bitonic,
    // cleaned by a 5-stage merge. Winner/partner slots are disjoint per step.
    for (int step = 1; step < nw64; step <<= 1) {
        bool winner = ((wid & (2 * step - 1)) == 0) && (wid + step < nw64);
        if (winner) {
            unsigned long long other = s[((wid + step) << 5) + (31 - lane)];
            key0 = key0 > other ? key0 : other;
            key0 = warp_merge_desc(key0, lane);
            s[(wid << 5) + lane] = key0;
        }
        __syncthreads();
    }

    // ---- warp 0 lane r holds rank-r key; publish indices ----
    const int kmax = min(K_TOP, size);
    if (wid == 0) {
        int lidx = (int)(~(unsigned int)(key0 & 0xFFFFFFFFull));
        tops[lane] = lidx;
        if (lane < K_TOP) {
            float idxval = (lane < kmax) ? (float)(offset + lidx) : -1.0f;
            out[(size_t)G * K_TOP * EMB_DIM + (size_t)g * K_TOP + lane] = idxval;
        }
    }
    __syncthreads();

    // ---- gather 30 rows x 128 f32: warp w owns rows {w, w+4, ..., w+28} ----
    // ALL of the warp's row loads issued back-to-back (MLP up to 8), then all
    // stores. Warps 0,1 have 8 rows; warps 2,3 have 7.
    {
        float4*       out4 = (float4*)(out + (size_t)g * K_TOP * EMB_DIM);
        const float4* emb4 = (const float4*)emb;
        const float4  zero = make_float4(0.f, 0.f, 0.f, 0.f);

        float4 vals[8];
        #pragma unroll
        for (int j = 0; j < 8; j++) {
            const int r = wid + 4 * j;
            const bool ok = (r < K_TOP);
            const int a = ok ? tops[r] : 0;
            vals[j] = (ok && r < kmax)
                    ? __ldg(&emb4[(size_t)(offset + a) * 32 + lane])
                    : zero;
        }
        #pragma unroll
        for (int j = 0; j < 8; j++) {
            const int r = wid + 4 * j;
            if (r < K_TOP) out4[r * 32 + lane] = vals[j];
        }
    }
}

extern "C" void kernel_launch(void* const* d_in, const int* in_sizes, int n_in,
                              void* d_out, int out_size) {
    const float* emb   = (const float*)d_in[0];
    const int*   sizes = (const int*)d_in[1];
    const int G = in_sizes[1];
    sortpool_kernel<<<G, NT>>>(emb, sizes, (float*)d_out, G);
}